// round 14
// baseline (speedup 1.0000x reference)
#include <cuda_runtime.h>
#include <cuda_bf16.h>
#include <cuda_fp16.h>
#include <cstdint>

#define B 4
#define N 4096
#define D 256
#define NW 64               // 64-bit words per bit-row
#define NT 32               // 128-token tiles per batch
#define NPAIR 528           // NT*(NT+1)/2 upper-tri tile pairs
#define SIM_THR 0.7f

typedef unsigned long long ull;

// ---------------- smem layout for sim kernel (bytes) ------------------------
// 256B rows, XOR-swizzled (16B-chunk index ^= row&7) -> ldmatrix conflict-free
#define ABUF (128 * 256)                // 32768
#define SM_A 0
#define SM_B (ABUF)
#define SM_BITS (2 * ABUF)              // 65536
#define SM_FLAG (SM_BITS + 256 * 8)
#define SIM_SMEM (SM_FLAG + 16)         // 67600 -> 3 CTAs/SM

// ---------------- smem layout for scan kernel (ull units) -------------------
#define SC_BUF  0
#define SC_SUP  4096
#define SC_FLG  (SC_SUP + 64)
#define SC_KM   (SC_FLG + 64)
#define SC_ANY  (SC_KM + 1)
#define SCAN_SMEM ((SC_ANY + 1) * 8)

// ---------------- device scratch (zero-initialized at module load) ----------
__device__ unsigned char g_sorted[(size_t)B * N * D];   // e4m3, sorted by score
__device__ int           g_order[B * N];                // rank -> original idx
__device__ int           g_invrank[B * N];              // original idx -> rank
__device__ ull           g_bits[(size_t)B * N * NW];
__device__ ull           g_blkflag[B][64];
__device__ ull           g_keepbits[B][64];             // bit i of word w: keep rank w*64+i

// ---------------- 1. rank by counting + flag reset ---------------------------
__global__ void rank_kernel(const float* __restrict__ scores) {
    __shared__ __align__(16) float s[N];
    const int b = blockIdx.x, chunk = blockIdx.y, tid = threadIdx.x;  // 128 thr
    if (chunk == 0 && tid < 64) g_blkflag[b][tid] = 0ull;
    const float* sc = scores + b * N;
    for (int t = tid; t < N; t += 128) s[t] = sc[t];
    __syncthreads();
    const int   idx = chunk * 128 + tid;
    const float si  = s[idx];
    const float4* s4 = (const float4*)s;
    int rank = 0;
    #pragma unroll 4
    for (int j4 = 0; j4 < N / 4; j4++) {
        const float4 v = s4[j4];
        const int j = j4 * 4;
        rank += (v.x > si) || (v.x == si && j     < idx);
        rank += (v.y > si) || (v.y == si && j + 1 < idx);
        rank += (v.z > si) || (v.z == si && j + 2 < idx);
        rank += (v.w > si) || (v.w == si && j + 3 < idx);
    }
    g_order[b * N + rank]  = idx;
    g_invrank[b * N + idx] = rank;
}

// ---------------- 2. normalize + gather (fp32 -> e4m3) ----------------------
__device__ __forceinline__ uint32_t pack_e4m3_4(float a, float b, float c, float d) {
    uint32_t r;
    asm("{\n\t.reg .b16 lo, hi;\n\t"
        "cvt.rn.satfinite.e4m3x2.f32 lo, %2, %1;\n\t"
        "cvt.rn.satfinite.e4m3x2.f32 hi, %4, %3;\n\t"
        "mov.b32 %0, {lo, hi};\n\t}"
        : "=r"(r) : "f"(a), "f"(b), "f"(c), "f"(d));
    return r;
}
__global__ void norm_gather_kernel(const float* __restrict__ tokens) {
    const int gw   = (blockIdx.x * blockDim.x + threadIdx.x) >> 5;
    const int lane = threadIdx.x & 31;
    if (gw >= B * N) return;
    const int src_i = g_order[gw];
    const int b     = gw / N;
    const float* src = tokens + ((size_t)b * N + src_i) * D;
    float4 v0 = *(const float4*)(src + lane * 8);
    float4 v1 = *(const float4*)(src + lane * 8 + 4);
    float ss = v0.x*v0.x + v0.y*v0.y + v0.z*v0.z + v0.w*v0.w
             + v1.x*v1.x + v1.y*v1.y + v1.z*v1.z + v1.w*v1.w;
    #pragma unroll
    for (int o = 16; o > 0; o >>= 1) ss += __shfl_xor_sync(0xffffffffu, ss, o);
    const float inv = 1.0f / (sqrtf(ss) + 1e-6f);
    uint2 u;
    u.x = pack_e4m3_4(v0.x * inv, v0.y * inv, v0.z * inv, v0.w * inv);
    u.y = pack_e4m3_4(v1.x * inv, v1.y * inv, v1.z * inv, v1.w * inv);
    *(uint2*)(g_sorted + (size_t)gw * D + lane * 8) = u;
}

// ---------------- 3. FP8 QMMA (f16 accum), swizzled smem, 3 CTAs/SM ---------
__device__ __forceinline__ void cp_async16(uint32_t saddr, const void* gaddr) {
    asm volatile("cp.async.cg.shared.global [%0], [%1], 16;"
                 :: "r"(saddr), "l"(gaddr));
}
__device__ __forceinline__ void ldm_x4(uint32_t& r0, uint32_t& r1,
                                       uint32_t& r2, uint32_t& r3, uint32_t addr) {
    asm volatile("ldmatrix.sync.aligned.m8n8.x4.shared.b16 {%0,%1,%2,%3}, [%4];"
                 : "=r"(r0), "=r"(r1), "=r"(r2), "=r"(r3) : "r"(addr));
}
__device__ __forceinline__ void qmma16832_h(uint32_t c[2], uint32_t a0, uint32_t a1,
                                            uint32_t a2, uint32_t a3,
                                            uint32_t b0, uint32_t b1) {
    asm volatile("mma.sync.aligned.m16n8k32.row.col.f16.e4m3.e4m3.f16 "
                 "{%0,%1}, {%2,%3,%4,%5}, {%6,%7}, {%0,%1};"
                 : "+r"(c[0]), "+r"(c[1])
                 : "r"(a0), "r"(a1), "r"(a2), "r"(a3), "r"(b0), "r"(b1));
}

__global__ void __launch_bounds__(256, 3) sim_bits_kernel() {
    int rem = blockIdx.x, ti = 0;
    while (rem >= NT - ti) { rem -= NT - ti; ti++; }
    const int tj = ti + rem;
    const int b  = blockIdx.y;

    extern __shared__ __align__(128) char sm[];
    const uint32_t smb = (uint32_t)__cvta_generic_to_shared(sm);
    ull*          sbits = (ull*)(sm + SM_BITS);
    unsigned int* sflag = (unsigned int*)(sm + SM_FLAG);

    const int tid = threadIdx.x, lane = tid & 31, wid = tid >> 5;
    const int wm = wid & 1, wn = wid >> 1;   // warp = m64 x n32

    const unsigned char* Ab = g_sorted + ((size_t)b * N + ti * 128) * D;
    const unsigned char* Bb = g_sorted + ((size_t)b * N + tj * 128) * D;

    // stage both tiles: 256B/row, 16B-chunk index XOR-swizzled by row&7
    #pragma unroll
    for (int l = 0; l < 8; l++) {
        const int e   = tid + l * 256;
        const int row = e >> 4;
        const int ch  = e & 15;
        const uint32_t so = (uint32_t)(row * 256 + ((ch ^ (row & 7)) << 4));
        cp_async16(smb + SM_A + so, Ab + row * D + ch * 16);
        cp_async16(smb + SM_B + so, Bb + row * D + ch * 16);
    }
    asm volatile("cp.async.commit_group;");

    sbits[tid] = 0ull;
    if (tid < 4) sflag[tid] = 0u;

    const bool live = !(ti == tj && (wn * 32 + 32) <= (wm * 64));

    // precomputed swizzled row bases
    uint32_t abase[4], bbase[2];
    int arx[4], brx[2];
    #pragma unroll
    for (int tm = 0; tm < 4; tm++) {
        const int row = wm * 64 + tm * 16 + (lane & 15);
        abase[tm] = smb + SM_A + (uint32_t)(row * 256);
        arx[tm]   = row & 7;
    }
    #pragma unroll
    for (int p = 0; p < 2; p++) {
        const int row = wn * 32 + p * 16 + (lane & 7) + ((lane >> 4) << 3);
        bbase[p] = smb + SM_B + (uint32_t)(row * 256);
        brx[p]   = row & 7;
    }

    uint32_t acc[4][4][2] = {};     // f16x2 accumulators

    asm volatile("cp.async.wait_group 0;");
    __syncthreads();

    if (live) {
        #pragma unroll
        for (int ks = 0; ks < 8; ks++) {
            const int ca = ks * 2 + (lane >> 4);          // A 16B-chunk
            const int cb = ks * 2 + ((lane >> 3) & 1);    // B 16B-chunk
            uint32_t a[4][4];
            #pragma unroll
            for (int tm = 0; tm < 4; tm++)
                ldm_x4(a[tm][0], a[tm][1], a[tm][2], a[tm][3],
                       abase[tm] + (uint32_t)((ca ^ arx[tm]) << 4));
            #pragma unroll
            for (int p = 0; p < 2; p++) {
                uint32_t b0, b1, b2, b3;
                ldm_x4(b0, b1, b2, b3, bbase[p] + (uint32_t)((cb ^ brx[p]) << 4));
                #pragma unroll
                for (int tm = 0; tm < 4; tm++) {
                    qmma16832_h(acc[tm][p*2],   a[tm][0], a[tm][1], a[tm][2], a[tm][3], b0, b1);
                    qmma16832_h(acc[tm][p*2+1], a[tm][0], a[tm][1], a[tm][2], a[tm][3], b2, b3);
                }
            }
        }

        const int word = wn >> 1;
        #pragma unroll
        for (int tm = 0; tm < 4; tm++) {
            const int r0  = wm * 64 + tm * 16 + (lane >> 2);
            const int r1  = r0 + 8;
            const int gi0 = ti * 128 + r0;
            const int gi1 = ti * 128 + r1;
            ull m0 = 0ull, m1 = 0ull;
            #pragma unroll
            for (int nt = 0; nt < 4; nt++) {
                const int lc = wn * 32 + nt * 8 + ((lane & 3) << 1);
                const int gj = tj * 128 + lc;
                const int bp = lc & 63;
                const float2 f0 = __half22float2(*reinterpret_cast<__half2*>(&acc[tm][nt][0]));
                const float2 f1 = __half22float2(*reinterpret_cast<__half2*>(&acc[tm][nt][1]));
                if (f0.x > SIM_THR && gj     > gi0) m0 |= 1ull << bp;
                if (f0.y > SIM_THR && gj + 1 > gi0) m0 |= 1ull << (bp + 1);
                if (f1.x > SIM_THR && gj     > gi1) m1 |= 1ull << bp;
                if (f1.y > SIM_THR && gj + 1 > gi1) m1 |= 1ull << (bp + 1);
            }
            if (m0) atomicOr(&sbits[r0 * 2 + word], m0);
            if (m1) atomicOr(&sbits[r1 * 2 + word], m1);
        }
    }
    __syncthreads();

    const int row = tid >> 1, w = tid & 1;
    const ull myword = sbits[tid];
    g_bits[((size_t)(b * N + ti * 128 + row)) * NW + tj * 2 + w] = myword;

    if (myword) atomicOr(&sflag[((row >> 6) << 1) | w], 1u);
    __syncthreads();
    if (tid < 4 && sflag[tid]) {
        const int rb = ti * 2 + (tid >> 1);
        const int wg = tj * 2 + (tid & 1);
        atomicOr(&g_blkflag[b][rb], 1ull << wg);
    }
}

// ---------------- 4. greedy scan -> keep bitmask (sorted order) -------------
__global__ void __launch_bounds__(1024, 1) scan_kernel() {
    extern __shared__ __align__(16) ull ssm[];
    ull*  buf      = ssm + SC_BUF;
    ull*  sup      = ssm + SC_SUP;
    ull*  flg      = ssm + SC_FLG;
    ull*  sh_keepm = ssm + SC_KM;
    ull*  sh_any   = ssm + SC_ANY;

    const int b   = blockIdx.x;
    const int tid = threadIdx.x;
    const ull* rows = g_bits + (size_t)b * N * NW;

    if (tid == 0) sh_any[0] = 0ull;
    if (tid < 64) { sup[tid] = 0ull; flg[tid] = g_blkflag[b][tid]; }
    __syncthreads();
    if (tid < 64 && flg[tid]) atomicOr(sh_any, 1ull);
    __syncthreads();

    if (sh_any[0] == 0ull) {               // nothing suppresses anything
        if (tid < 64) g_keepbits[b][tid] = ~0ull;
        return;
    }

    const uint32_t smb = (uint32_t)__cvta_generic_to_shared(ssm);

    for (int wb = 0; wb < 64; wb++) {
        const ull fl = flg[wb];
        if (fl == 0ull) {
            if (tid == 0) g_keepbits[b][wb] = ~sup[wb];
            continue;
        }

        {
            const char* src = (const char*)(rows + (size_t)wb * 64 * NW);
            cp_async16(smb + (uint32_t)tid * 16,          src + tid * 16);
            cp_async16(smb + (uint32_t)(tid + 1024) * 16, src + (tid + 1024) * 16);
            asm volatile("cp.async.commit_group;");
            asm volatile("cp.async.wait_group 0;");
        }
        __syncthreads();

        if (tid < 32) {
            ull supw = sup[wb];
            ull keepm;
            if (((fl >> wb) & 1ull) == 0ull) {
                keepm = ~supw;
            } else {
                keepm = 0ull;                       // redundant per-lane chain
                #pragma unroll 8
                for (int i = 0; i < 64; i++) {
                    const ull d = buf[i * 64 + wb];
                    const bool k = ((supw >> i) & 1ull) == 0ull;
                    if (k) { supw |= d; keepm |= 1ull << i; }
                }
            }
            if (tid == 0) { sh_keepm[0] = keepm; g_keepbits[b][wb] = keepm; }
        }
        __syncthreads();

        const ull keepm = sh_keepm[0];
        const int w   = tid & 63;
        const int sub = tid >> 6;
        if (w > wb && ((fl >> w) & 1ull)) {
            ull p = 0ull;
            #pragma unroll
            for (int r = 0; r < 4; r++) {
                const int i = sub * 4 + r;
                if ((keepm >> i) & 1ull) p |= buf[i * 64 + w];
            }
            if (p) atomicOr(&sup[w], p);
        }
        __syncthreads();
    }
}

// ---------------- 5. masked tokens (ILP=4) + keep tail ----------------------
#define MASK_Q (B * N * (D / 4) / 4)    // 262144 threads, 4 float4 each

__global__ void mask_kernel(const float4* __restrict__ tok, float* __restrict__ out,
                            int tail_count) {
    const int tid = blockIdx.x * blockDim.x + threadIdx.x;
    if (tid < MASK_Q) {
        // 4 independent element chains at stride MASK_Q (coalesced, MLP=4)
        float4 v[4];
        float  k[4];
        #pragma unroll
        for (int u = 0; u < 4; u++) {
            const int idx   = tid + u * MASK_Q;
            const int token = idx >> 6;            // D/4 = 64 float4 per token
            const int b     = token >> 12;         // N = 4096
            const int r     = g_invrank[token];
            k[u] = ((g_keepbits[b][r >> 6] >> (r & 63)) & 1ull) ? 1.0f : 0.0f;
            v[u] = tok[idx];
        }
        #pragma unroll
        for (int u = 0; u < 4; u++) {
            const int idx = tid + u * MASK_Q;
            float4 o = v[u];
            o.x *= k[u]; o.y *= k[u]; o.z *= k[u]; o.w *= k[u];
            ((float4*)out)[idx] = o;
        }
    } else {
        const int t = tid - MASK_Q;                // tail: keep floats, original order
        if (t < tail_count) {
            const int b = t >> 12;
            const int r = g_invrank[t];
            out[(size_t)B * N * D + t] =
                ((g_keepbits[b][r >> 6] >> (r & 63)) & 1ull) ? 1.0f : 0.0f;
        }
    }
}

// ---------------- launch -----------------------------------------------------
extern "C" void kernel_launch(void* const* d_in, const int* in_sizes, int n_in,
                              void* d_out, int out_size) {
    const float* tokens = (const float*)d_in[0];
    const float* scores = (const float*)d_in[1];
    float* out = (float*)d_out;

    cudaFuncSetAttribute(sim_bits_kernel,
                         cudaFuncAttributeMaxDynamicSharedMemorySize, SIM_SMEM);
    cudaFuncSetAttribute(scan_kernel,
                         cudaFuncAttributeMaxDynamicSharedMemorySize, SCAN_SMEM);

    { dim3 grid(B, 32); rank_kernel<<<grid, 128>>>(scores); }

    {
        const int warps  = B * N;
        const int blocks = (warps * 32 + 255) / 256;
        norm_gather_kernel<<<blocks, 256>>>(tokens);
    }

    { dim3 grid(NPAIR, B); sim_bits_kernel<<<grid, 256, SIM_SMEM>>>(); }

    scan_kernel<<<B, 1024, SCAN_SMEM>>>();

    {
        const long long bnd = (long long)B * N * D;
        int tail = 0;
        if ((long long)out_size > bnd) {
            tail = (int)((long long)out_size - bnd);
            if (tail > B * N) tail = B * N;
        }
        const int total = MASK_Q + tail;
        mask_kernel<<<(total + 255) / 256, 256>>>((const float4*)tokens, out, tail);
    }
}

// round 15
// speedup vs baseline: 1.0595x; 1.0595x over previous
#include <cuda_runtime.h>
#include <cuda_bf16.h>
#include <cuda_fp16.h>
#include <cstdint>

#define B 4
#define N 4096
#define D 256
#define NW 64               // 64-bit words per bit-row
#define NT 32               // 128-token tiles per batch
#define NPAIR 528           // NT*(NT+1)/2 upper-tri tile pairs
#define SIM_THR 0.7f

typedef unsigned long long ull;

// ---------------- smem layout for sim kernel (bytes) ------------------------
// 256B rows, XOR-swizzled (16B-chunk index ^= row&7) -> ldmatrix conflict-free
#define ABUF (128 * 256)                // 32768
#define SM_A 0
#define SM_B (ABUF)
#define SM_BITS (2 * ABUF)              // 65536
#define SM_FLAG (SM_BITS + 256 * 8)
#define SIM_SMEM (SM_FLAG + 16)         // 67600 -> 3 CTAs/SM

// ---------------- smem layout for scan kernel (ull units) -------------------
#define SC_BUF  0
#define SC_SUP  4096
#define SC_FLG  (SC_SUP + 64)
#define SC_KM   (SC_FLG + 64)
#define SC_ANY  (SC_KM + 1)
#define SCAN_SMEM ((SC_ANY + 1) * 8)

// ---------------- device scratch (zero-initialized at module load) ----------
__device__ unsigned char g_sorted[(size_t)B * N * D];   // e4m3, sorted by score
__device__ int           g_order[B * N];                // rank -> original idx
__device__ int           g_invrank[B * N];              // original idx -> rank
__device__ ull           g_bits[(size_t)B * N * NW];
__device__ ull           g_blkflag[B][64];
__device__ ull           g_keepbits[B][64];             // bit i of word w: keep rank w*64+i

// ---------------- 1. rank by counting (segmented, 512 thr) + flag reset -----
__global__ void __launch_bounds__(512) rank_kernel(const float* __restrict__ scores) {
    __shared__ __align__(16) float s[N];
    __shared__ int part[512];
    const int b = blockIdx.x, chunk = blockIdx.y, tid = threadIdx.x;  // 512 thr
    if (chunk == 0 && tid < 64) g_blkflag[b][tid] = 0ull;
    const float* sc = scores + b * N;
    for (int t = tid; t < N; t += 512) s[t] = sc[t];
    __syncthreads();

    const int lt  = tid & 127;             // token within chunk
    const int seg = tid >> 7;              // score segment 0..3 (1024 each)
    const int idx = chunk * 128 + lt;
    const float si = s[idx];
    const float4* s4 = (const float4*)s + seg * 256;
    const int jbase = seg * 1024;
    int r = 0;
    #pragma unroll 4
    for (int j4 = 0; j4 < 256; j4++) {
        const float4 v = s4[j4];
        const int j = jbase + j4 * 4;
        r += (v.x > si) || (v.x == si && j     < idx);
        r += (v.y > si) || (v.y == si && j + 1 < idx);
        r += (v.z > si) || (v.z == si && j + 2 < idx);
        r += (v.w > si) || (v.w == si && j + 3 < idx);
    }
    part[tid] = r;
    __syncthreads();

    if (tid < 128) {
        const int rank = part[tid] + part[tid + 128] + part[tid + 256] + part[tid + 384];
        const int gidx = chunk * 128 + tid;
        g_order[b * N + rank]   = gidx;
        g_invrank[b * N + gidx] = rank;
    }
}

// ---------------- 2. normalize + gather (fp32 -> e4m3) ----------------------
__device__ __forceinline__ uint32_t pack_e4m3_4(float a, float b, float c, float d) {
    uint32_t r;
    asm("{\n\t.reg .b16 lo, hi;\n\t"
        "cvt.rn.satfinite.e4m3x2.f32 lo, %2, %1;\n\t"
        "cvt.rn.satfinite.e4m3x2.f32 hi, %4, %3;\n\t"
        "mov.b32 %0, {lo, hi};\n\t}"
        : "=r"(r) : "f"(a), "f"(b), "f"(c), "f"(d));
    return r;
}
__global__ void norm_gather_kernel(const float* __restrict__ tokens) {
    const int gw   = (blockIdx.x * blockDim.x + threadIdx.x) >> 5;
    const int lane = threadIdx.x & 31;
    if (gw >= B * N) return;
    const int src_i = g_order[gw];
    const int b     = gw / N;
    const float* src = tokens + ((size_t)b * N + src_i) * D;
    float4 v0 = *(const float4*)(src + lane * 8);
    float4 v1 = *(const float4*)(src + lane * 8 + 4);
    float ss = v0.x*v0.x + v0.y*v0.y + v0.z*v0.z + v0.w*v0.w
             + v1.x*v1.x + v1.y*v1.y + v1.z*v1.z + v1.w*v1.w;
    #pragma unroll
    for (int o = 16; o > 0; o >>= 1) ss += __shfl_xor_sync(0xffffffffu, ss, o);
    const float inv = 1.0f / (sqrtf(ss) + 1e-6f);
    uint2 u;
    u.x = pack_e4m3_4(v0.x * inv, v0.y * inv, v0.z * inv, v0.w * inv);
    u.y = pack_e4m3_4(v1.x * inv, v1.y * inv, v1.z * inv, v1.w * inv);
    *(uint2*)(g_sorted + (size_t)gw * D + lane * 8) = u;
}

// ---------------- 3. FP8 QMMA (f16 accum), swizzled smem, 3 CTAs/SM ---------
__device__ __forceinline__ void cp_async16(uint32_t saddr, const void* gaddr) {
    asm volatile("cp.async.cg.shared.global [%0], [%1], 16;"
                 :: "r"(saddr), "l"(gaddr));
}
__device__ __forceinline__ void ldm_x4(uint32_t& r0, uint32_t& r1,
                                       uint32_t& r2, uint32_t& r3, uint32_t addr) {
    asm volatile("ldmatrix.sync.aligned.m8n8.x4.shared.b16 {%0,%1,%2,%3}, [%4];"
                 : "=r"(r0), "=r"(r1), "=r"(r2), "=r"(r3) : "r"(addr));
}
__device__ __forceinline__ void qmma16832_h(uint32_t c[2], uint32_t a0, uint32_t a1,
                                            uint32_t a2, uint32_t a3,
                                            uint32_t b0, uint32_t b1) {
    asm volatile("mma.sync.aligned.m16n8k32.row.col.f16.e4m3.e4m3.f16 "
                 "{%0,%1}, {%2,%3,%4,%5}, {%6,%7}, {%0,%1};"
                 : "+r"(c[0]), "+r"(c[1])
                 : "r"(a0), "r"(a1), "r"(a2), "r"(a3), "r"(b0), "r"(b1));
}

__global__ void __launch_bounds__(256, 3) sim_bits_kernel() {
    int rem = blockIdx.x, ti = 0;
    while (rem >= NT - ti) { rem -= NT - ti; ti++; }
    const int tj = ti + rem;
    const int b  = blockIdx.y;

    extern __shared__ __align__(128) char sm[];
    const uint32_t smb = (uint32_t)__cvta_generic_to_shared(sm);
    ull*          sbits = (ull*)(sm + SM_BITS);
    unsigned int* sflag = (unsigned int*)(sm + SM_FLAG);

    const int tid = threadIdx.x, lane = tid & 31, wid = tid >> 5;
    const int wm = wid & 1, wn = wid >> 1;   // warp = m64 x n32

    const unsigned char* Ab = g_sorted + ((size_t)b * N + ti * 128) * D;
    const unsigned char* Bb = g_sorted + ((size_t)b * N + tj * 128) * D;

    // stage both tiles: 256B/row, 16B-chunk index XOR-swizzled by row&7
    #pragma unroll
    for (int l = 0; l < 8; l++) {
        const int e   = tid + l * 256;
        const int row = e >> 4;
        const int ch  = e & 15;
        const uint32_t so = (uint32_t)(row * 256 + ((ch ^ (row & 7)) << 4));
        cp_async16(smb + SM_A + so, Ab + row * D + ch * 16);
        cp_async16(smb + SM_B + so, Bb + row * D + ch * 16);
    }
    asm volatile("cp.async.commit_group;");

    sbits[tid] = 0ull;
    if (tid < 4) sflag[tid] = 0u;

    const bool live = !(ti == tj && (wn * 32 + 32) <= (wm * 64));

    // precomputed swizzled row bases
    uint32_t abase[4], bbase[2];
    int arx[4], brx[2];
    #pragma unroll
    for (int tm = 0; tm < 4; tm++) {
        const int row = wm * 64 + tm * 16 + (lane & 15);
        abase[tm] = smb + SM_A + (uint32_t)(row * 256);
        arx[tm]   = row & 7;
    }
    #pragma unroll
    for (int p = 0; p < 2; p++) {
        const int row = wn * 32 + p * 16 + (lane & 7) + ((lane >> 4) << 3);
        bbase[p] = smb + SM_B + (uint32_t)(row * 256);
        brx[p]   = row & 7;
    }

    uint32_t acc[4][4][2] = {};     // f16x2 accumulators

    asm volatile("cp.async.wait_group 0;");
    __syncthreads();

    if (live) {
        #pragma unroll
        for (int ks = 0; ks < 8; ks++) {
            const int ca = ks * 2 + (lane >> 4);          // A 16B-chunk
            const int cb = ks * 2 + ((lane >> 3) & 1);    // B 16B-chunk
            uint32_t a[4][4];
            #pragma unroll
            for (int tm = 0; tm < 4; tm++)
                ldm_x4(a[tm][0], a[tm][1], a[tm][2], a[tm][3],
                       abase[tm] + (uint32_t)((ca ^ arx[tm]) << 4));
            #pragma unroll
            for (int p = 0; p < 2; p++) {
                uint32_t b0, b1, b2, b3;
                ldm_x4(b0, b1, b2, b3, bbase[p] + (uint32_t)((cb ^ brx[p]) << 4));
                #pragma unroll
                for (int tm = 0; tm < 4; tm++) {
                    qmma16832_h(acc[tm][p*2],   a[tm][0], a[tm][1], a[tm][2], a[tm][3], b0, b1);
                    qmma16832_h(acc[tm][p*2+1], a[tm][0], a[tm][1], a[tm][2], a[tm][3], b2, b3);
                }
            }
        }

        const int word = wn >> 1;
        #pragma unroll
        for (int tm = 0; tm < 4; tm++) {
            const int r0  = wm * 64 + tm * 16 + (lane >> 2);
            const int r1  = r0 + 8;
            const int gi0 = ti * 128 + r0;
            const int gi1 = ti * 128 + r1;
            ull m0 = 0ull, m1 = 0ull;
            #pragma unroll
            for (int nt = 0; nt < 4; nt++) {
                const int lc = wn * 32 + nt * 8 + ((lane & 3) << 1);
                const int gj = tj * 128 + lc;
                const int bp = lc & 63;
                const float2 f0 = __half22float2(*reinterpret_cast<__half2*>(&acc[tm][nt][0]));
                const float2 f1 = __half22float2(*reinterpret_cast<__half2*>(&acc[tm][nt][1]));
                if (f0.x > SIM_THR && gj     > gi0) m0 |= 1ull << bp;
                if (f0.y > SIM_THR && gj + 1 > gi0) m0 |= 1ull << (bp + 1);
                if (f1.x > SIM_THR && gj     > gi1) m1 |= 1ull << bp;
                if (f1.y > SIM_THR && gj + 1 > gi1) m1 |= 1ull << (bp + 1);
            }
            if (m0) atomicOr(&sbits[r0 * 2 + word], m0);
            if (m1) atomicOr(&sbits[r1 * 2 + word], m1);
        }
    }
    __syncthreads();

    const int row = tid >> 1, w = tid & 1;
    const ull myword = sbits[tid];
    g_bits[((size_t)(b * N + ti * 128 + row)) * NW + tj * 2 + w] = myword;

    if (myword) atomicOr(&sflag[((row >> 6) << 1) | w], 1u);
    __syncthreads();
    if (tid < 4 && sflag[tid]) {
        const int rb = ti * 2 + (tid >> 1);
        const int wg = tj * 2 + (tid & 1);
        atomicOr(&g_blkflag[b][rb], 1ull << wg);
    }
}

// ---------------- 4. greedy scan -> keep bitmask (sorted order) -------------
__global__ void __launch_bounds__(1024, 1) scan_kernel() {
    extern __shared__ __align__(16) ull ssm[];
    ull*  buf      = ssm + SC_BUF;
    ull*  sup      = ssm + SC_SUP;
    ull*  flg      = ssm + SC_FLG;
    ull*  sh_keepm = ssm + SC_KM;
    ull*  sh_any   = ssm + SC_ANY;

    const int b   = blockIdx.x;
    const int tid = threadIdx.x;
    const ull* rows = g_bits + (size_t)b * N * NW;

    if (tid == 0) sh_any[0] = 0ull;
    if (tid < 64) { sup[tid] = 0ull; flg[tid] = g_blkflag[b][tid]; }
    __syncthreads();
    if (tid < 64 && flg[tid]) atomicOr(sh_any, 1ull);
    __syncthreads();

    if (sh_any[0] == 0ull) {               // nothing suppresses anything
        if (tid < 64) g_keepbits[b][tid] = ~0ull;
        return;
    }

    const uint32_t smb = (uint32_t)__cvta_generic_to_shared(ssm);

    for (int wb = 0; wb < 64; wb++) {
        const ull fl = flg[wb];
        if (fl == 0ull) {
            if (tid == 0) g_keepbits[b][wb] = ~sup[wb];
            continue;
        }

        {
            const char* src = (const char*)(rows + (size_t)wb * 64 * NW);
            cp_async16(smb + (uint32_t)tid * 16,          src + tid * 16);
            cp_async16(smb + (uint32_t)(tid + 1024) * 16, src + (tid + 1024) * 16);
            asm volatile("cp.async.commit_group;");
            asm volatile("cp.async.wait_group 0;");
        }
        __syncthreads();

        if (tid < 32) {
            ull supw = sup[wb];
            ull keepm;
            if (((fl >> wb) & 1ull) == 0ull) {
                keepm = ~supw;
            } else {
                keepm = 0ull;                       // redundant per-lane chain
                #pragma unroll 8
                for (int i = 0; i < 64; i++) {
                    const ull d = buf[i * 64 + wb];
                    const bool k = ((supw >> i) & 1ull) == 0ull;
                    if (k) { supw |= d; keepm |= 1ull << i; }
                }
            }
            if (tid == 0) { sh_keepm[0] = keepm; g_keepbits[b][wb] = keepm; }
        }
        __syncthreads();

        const ull keepm = sh_keepm[0];
        const int w   = tid & 63;
        const int sub = tid >> 6;
        if (w > wb && ((fl >> w) & 1ull)) {
            ull p = 0ull;
            #pragma unroll
            for (int r = 0; r < 4; r++) {
                const int i = sub * 4 + r;
                if ((keepm >> i) & 1ull) p |= buf[i * 64 + w];
            }
            if (p) atomicOr(&sup[w], p);
        }
        __syncthreads();
    }
}

// ---------------- 5. masked tokens + keep tail in one kernel ----------------
__global__ void mask_kernel(const float4* __restrict__ tok, float* __restrict__ out,
                            int tail_count) {
    const int idx = blockIdx.x * blockDim.x + threadIdx.x;
    const int total4 = B * N * (D / 4);
    if (idx < total4) {
        const int token = idx >> 6;                // D/4 = 64 float4 per token
        const int b     = token >> 12;             // N = 4096
        const int r     = g_invrank[token];
        const float k   = ((g_keepbits[b][r >> 6] >> (r & 63)) & 1ull) ? 1.0f : 0.0f;
        float4 v = tok[idx];
        v.x *= k; v.y *= k; v.z *= k; v.w *= k;
        ((float4*)out)[idx] = v;
    } else {
        const int t = idx - total4;                // tail: keep floats, original order
        if (t < tail_count) {
            const int b = t >> 12;
            const int r = g_invrank[t];
            out[(size_t)B * N * D + t] =
                ((g_keepbits[b][r >> 6] >> (r & 63)) & 1ull) ? 1.0f : 0.0f;
        }
    }
}

// ---------------- launch -----------------------------------------------------
extern "C" void kernel_launch(void* const* d_in, const int* in_sizes, int n_in,
                              void* d_out, int out_size) {
    const float* tokens = (const float*)d_in[0];
    const float* scores = (const float*)d_in[1];
    float* out = (float*)d_out;

    cudaFuncSetAttribute(sim_bits_kernel,
                         cudaFuncAttributeMaxDynamicSharedMemorySize, SIM_SMEM);
    cudaFuncSetAttribute(scan_kernel,
                         cudaFuncAttributeMaxDynamicSharedMemorySize, SCAN_SMEM);

    { dim3 grid(B, 32); rank_kernel<<<grid, 512>>>(scores); }

    {
        const int warps  = B * N;
        const int blocks = (warps * 32 + 255) / 256;
        norm_gather_kernel<<<blocks, 256>>>(tokens);
    }

    { dim3 grid(NPAIR, B); sim_bits_kernel<<<grid, 256, SIM_SMEM>>>(); }

    scan_kernel<<<B, 1024, SCAN_SMEM>>>();

    {
        const long long bnd = (long long)B * N * D;
        int tail = 0;
        if ((long long)out_size > bnd) {
            tail = (int)((long long)out_size - bnd);
            if (tail > B * N) tail = B * N;
        }
        const int total = B * N * (D / 4) + tail;
        mask_kernel<<<(total + 255) / 256, 256>>>((const float4*)tokens, out, tail);
    }
}

// round 16
// speedup vs baseline: 1.0640x; 1.0042x over previous
#include <cuda_runtime.h>
#include <cuda_bf16.h>
#include <cuda_fp16.h>
#include <cstdint>

#define B 4
#define N 4096
#define D 256
#define NW 64               // 64-bit words per bit-row
#define NT 32               // 128-token tiles per batch
#define NPAIR 528           // NT*(NT+1)/2 upper-tri tile pairs
#define SIM_THR 0.7f

typedef unsigned long long ull;

// ---------------- smem layout for sim kernel (bytes) ------------------------
// 256B rows, XOR-swizzled (16B-chunk index ^= row&7) -> ldmatrix conflict-free
#define ABUF (128 * 256)                // 32768
#define SM_A 0
#define SM_B (ABUF)
#define SM_BITS (2 * ABUF)              // 65536
#define SM_FLAG (SM_BITS + 256 * 8)
#define SIM_SMEM (SM_FLAG + 16)         // 67600 -> 3 CTAs/SM

// ---------------- smem layout for scan kernel (ull units) -------------------
#define SC_BUF  0
#define SC_SUP  4096
#define SC_FLG  (SC_SUP + 64)
#define SC_KM   (SC_FLG + 64)
#define SC_ANY  (SC_KM + 1)
#define SC_ORD  (SC_ANY + 1)            // int[4096] staged order
#define SCAN_SMEM ((SC_ORD + 2048) * 8)

// ---------------- device scratch (zero-initialized at module load) ----------
__device__ unsigned char g_sorted[(size_t)B * N * D];   // e4m3, sorted by score
__device__ int           g_order[B * N];                // rank -> original idx
__device__ ull           g_bits[(size_t)B * N * NW];
__device__ ull           g_blkflag[B][64];
__device__ float         g_keepf[B * N];                // keep mask, ORIGINAL order

// ---------------- 1. rank by counting (segmented, 512 thr) + flag reset -----
__global__ void __launch_bounds__(512) rank_kernel(const float* __restrict__ scores) {
    __shared__ __align__(16) float s[N];
    __shared__ int part[512];
    const int b = blockIdx.x, chunk = blockIdx.y, tid = threadIdx.x;  // 512 thr
    if (chunk == 0 && tid < 64) g_blkflag[b][tid] = 0ull;
    const float* sc = scores + b * N;
    for (int t = tid; t < N; t += 512) s[t] = sc[t];
    __syncthreads();

    const int lt  = tid & 127;             // token within chunk
    const int seg = tid >> 7;              // score segment 0..3 (1024 each)
    const int idx = chunk * 128 + lt;
    const float si = s[idx];
    const float4* s4 = (const float4*)s + seg * 256;
    const int jbase = seg * 1024;
    int r = 0;
    #pragma unroll 4
    for (int j4 = 0; j4 < 256; j4++) {
        const float4 v = s4[j4];
        const int j = jbase + j4 * 4;
        r += (v.x > si) || (v.x == si && j     < idx);
        r += (v.y > si) || (v.y == si && j + 1 < idx);
        r += (v.z > si) || (v.z == si && j + 2 < idx);
        r += (v.w > si) || (v.w == si && j + 3 < idx);
    }
    part[tid] = r;
    __syncthreads();

    if (tid < 128) {
        const int rank = part[tid] + part[tid + 128] + part[tid + 256] + part[tid + 384];
        const int gidx = chunk * 128 + tid;
        g_order[b * N + rank] = gidx;
    }
}

// ---------------- 2. normalize + gather (fp32 -> e4m3) ----------------------
__device__ __forceinline__ uint32_t pack_e4m3_4(float a, float b, float c, float d) {
    uint32_t r;
    asm("{\n\t.reg .b16 lo, hi;\n\t"
        "cvt.rn.satfinite.e4m3x2.f32 lo, %2, %1;\n\t"
        "cvt.rn.satfinite.e4m3x2.f32 hi, %4, %3;\n\t"
        "mov.b32 %0, {lo, hi};\n\t}"
        : "=r"(r) : "f"(a), "f"(b), "f"(c), "f"(d));
    return r;
}
__global__ void norm_gather_kernel(const float* __restrict__ tokens) {
    const int gw   = (blockIdx.x * blockDim.x + threadIdx.x) >> 5;
    const int lane = threadIdx.x & 31;
    if (gw >= B * N) return;
    const int src_i = g_order[gw];
    const int b     = gw / N;
    const float* src = tokens + ((size_t)b * N + src_i) * D;
    float4 v0 = *(const float4*)(src + lane * 8);
    float4 v1 = *(const float4*)(src + lane * 8 + 4);
    float ss = v0.x*v0.x + v0.y*v0.y + v0.z*v0.z + v0.w*v0.w
             + v1.x*v1.x + v1.y*v1.y + v1.z*v1.z + v1.w*v1.w;
    #pragma unroll
    for (int o = 16; o > 0; o >>= 1) ss += __shfl_xor_sync(0xffffffffu, ss, o);
    const float inv = 1.0f / (sqrtf(ss) + 1e-6f);
    uint2 u;
    u.x = pack_e4m3_4(v0.x * inv, v0.y * inv, v0.z * inv, v0.w * inv);
    u.y = pack_e4m3_4(v1.x * inv, v1.y * inv, v1.z * inv, v1.w * inv);
    *(uint2*)(g_sorted + (size_t)gw * D + lane * 8) = u;
}

// ---------------- 3. FP8 QMMA (f16 accum), swizzled smem, 3 CTAs/SM ---------
__device__ __forceinline__ void cp_async16(uint32_t saddr, const void* gaddr) {
    asm volatile("cp.async.cg.shared.global [%0], [%1], 16;"
                 :: "r"(saddr), "l"(gaddr));
}
__device__ __forceinline__ void ldm_x4(uint32_t& r0, uint32_t& r1,
                                       uint32_t& r2, uint32_t& r3, uint32_t addr) {
    asm volatile("ldmatrix.sync.aligned.m8n8.x4.shared.b16 {%0,%1,%2,%3}, [%4];"
                 : "=r"(r0), "=r"(r1), "=r"(r2), "=r"(r3) : "r"(addr));
}
__device__ __forceinline__ void qmma16832_h(uint32_t c[2], uint32_t a0, uint32_t a1,
                                            uint32_t a2, uint32_t a3,
                                            uint32_t b0, uint32_t b1) {
    asm volatile("mma.sync.aligned.m16n8k32.row.col.f16.e4m3.e4m3.f16 "
                 "{%0,%1}, {%2,%3,%4,%5}, {%6,%7}, {%0,%1};"
                 : "+r"(c[0]), "+r"(c[1])
                 : "r"(a0), "r"(a1), "r"(a2), "r"(a3), "r"(b0), "r"(b1));
}

__global__ void __launch_bounds__(256, 3) sim_bits_kernel() {
    int rem = blockIdx.x, ti = 0;
    while (rem >= NT - ti) { rem -= NT - ti; ti++; }
    const int tj = ti + rem;
    const int b  = blockIdx.y;

    extern __shared__ __align__(128) char sm[];
    const uint32_t smb = (uint32_t)__cvta_generic_to_shared(sm);
    ull*          sbits = (ull*)(sm + SM_BITS);
    unsigned int* sflag = (unsigned int*)(sm + SM_FLAG);

    const int tid = threadIdx.x, lane = tid & 31, wid = tid >> 5;
    const int wm = wid & 1, wn = wid >> 1;   // warp = m64 x n32

    const unsigned char* Ab = g_sorted + ((size_t)b * N + ti * 128) * D;
    const unsigned char* Bb = g_sorted + ((size_t)b * N + tj * 128) * D;

    // stage both tiles: 256B/row, 16B-chunk index XOR-swizzled by row&7
    #pragma unroll
    for (int l = 0; l < 8; l++) {
        const int e   = tid + l * 256;
        const int row = e >> 4;
        const int ch  = e & 15;
        const uint32_t so = (uint32_t)(row * 256 + ((ch ^ (row & 7)) << 4));
        cp_async16(smb + SM_A + so, Ab + row * D + ch * 16);
        cp_async16(smb + SM_B + so, Bb + row * D + ch * 16);
    }
    asm volatile("cp.async.commit_group;");

    sbits[tid] = 0ull;
    if (tid < 4) sflag[tid] = 0u;

    const bool live = !(ti == tj && (wn * 32 + 32) <= (wm * 64));

    // precomputed swizzled row bases
    uint32_t abase[4], bbase[2];
    int arx[4], brx[2];
    #pragma unroll
    for (int tm = 0; tm < 4; tm++) {
        const int row = wm * 64 + tm * 16 + (lane & 15);
        abase[tm] = smb + SM_A + (uint32_t)(row * 256);
        arx[tm]   = row & 7;
    }
    #pragma unroll
    for (int p = 0; p < 2; p++) {
        const int row = wn * 32 + p * 16 + (lane & 7) + ((lane >> 4) << 3);
        bbase[p] = smb + SM_B + (uint32_t)(row * 256);
        brx[p]   = row & 7;
    }

    uint32_t acc[4][4][2] = {};     // f16x2 accumulators

    asm volatile("cp.async.wait_group 0;");
    __syncthreads();

    if (live) {
        #pragma unroll
        for (int ks = 0; ks < 8; ks++) {
            const int ca = ks * 2 + (lane >> 4);          // A 16B-chunk
            const int cb = ks * 2 + ((lane >> 3) & 1);    // B 16B-chunk
            uint32_t a[4][4];
            #pragma unroll
            for (int tm = 0; tm < 4; tm++)
                ldm_x4(a[tm][0], a[tm][1], a[tm][2], a[tm][3],
                       abase[tm] + (uint32_t)((ca ^ arx[tm]) << 4));
            #pragma unroll
            for (int p = 0; p < 2; p++) {
                uint32_t b0, b1, b2, b3;
                ldm_x4(b0, b1, b2, b3, bbase[p] + (uint32_t)((cb ^ brx[p]) << 4));
                #pragma unroll
                for (int tm = 0; tm < 4; tm++) {
                    qmma16832_h(acc[tm][p*2],   a[tm][0], a[tm][1], a[tm][2], a[tm][3], b0, b1);
                    qmma16832_h(acc[tm][p*2+1], a[tm][0], a[tm][1], a[tm][2], a[tm][3], b2, b3);
                }
            }
        }

        const int word = wn >> 1;
        #pragma unroll
        for (int tm = 0; tm < 4; tm++) {
            const int r0  = wm * 64 + tm * 16 + (lane >> 2);
            const int r1  = r0 + 8;
            const int gi0 = ti * 128 + r0;
            const int gi1 = ti * 128 + r1;
            ull m0 = 0ull, m1 = 0ull;
            #pragma unroll
            for (int nt = 0; nt < 4; nt++) {
                const int lc = wn * 32 + nt * 8 + ((lane & 3) << 1);
                const int gj = tj * 128 + lc;
                const int bp = lc & 63;
                const float2 f0 = __half22float2(*reinterpret_cast<__half2*>(&acc[tm][nt][0]));
                const float2 f1 = __half22float2(*reinterpret_cast<__half2*>(&acc[tm][nt][1]));
                if (f0.x > SIM_THR && gj     > gi0) m0 |= 1ull << bp;
                if (f0.y > SIM_THR && gj + 1 > gi0) m0 |= 1ull << (bp + 1);
                if (f1.x > SIM_THR && gj     > gi1) m1 |= 1ull << bp;
                if (f1.y > SIM_THR && gj + 1 > gi1) m1 |= 1ull << (bp + 1);
            }
            if (m0) atomicOr(&sbits[r0 * 2 + word], m0);
            if (m1) atomicOr(&sbits[r1 * 2 + word], m1);
        }
    }
    __syncthreads();

    const int row = tid >> 1, w = tid & 1;
    const ull myword = sbits[tid];
    g_bits[((size_t)(b * N + ti * 128 + row)) * NW + tj * 2 + w] = myword;

    if (myword) atomicOr(&sflag[((row >> 6) << 1) | w], 1u);
    __syncthreads();
    if (tid < 4 && sflag[tid]) {
        const int rb = ti * 2 + (tid >> 1);
        const int wg = tj * 2 + (tid & 1);
        atomicOr(&g_blkflag[b][rb], 1ull << wg);
    }
}

// ---------------- 4. greedy scan -> keep floats in ORIGINAL order -----------
__global__ void __launch_bounds__(1024, 1) scan_kernel() {
    extern __shared__ __align__(16) ull ssm[];
    ull*  buf      = ssm + SC_BUF;
    ull*  sup      = ssm + SC_SUP;
    ull*  flg      = ssm + SC_FLG;
    ull*  sh_keepm = ssm + SC_KM;
    ull*  sh_any   = ssm + SC_ANY;
    int*  sord     = (int*)(ssm + SC_ORD);

    const int b   = blockIdx.x;
    const int tid = threadIdx.x;
    const ull* rows = g_bits + (size_t)b * N * NW;
    float*     keepf = g_keepf + b * N;

    if (tid == 0) sh_any[0] = 0ull;
    if (tid < 64) { sup[tid] = 0ull; flg[tid] = g_blkflag[b][tid]; }
    __syncthreads();
    if (tid < 64 && flg[tid]) atomicOr(sh_any, 1ull);
    __syncthreads();

    if (sh_any[0] == 0ull) {               // nothing suppresses anything
        #pragma unroll
        for (int l = 0; l < 4; l++) keepf[tid + l * 1024] = 1.0f;
        return;
    }

    const int* order = g_order + b * N;
    #pragma unroll
    for (int l = 0; l < 4; l++) sord[tid + l * 1024] = order[tid + l * 1024];

    const uint32_t smb = (uint32_t)__cvta_generic_to_shared(ssm);

    for (int wb = 0; wb < 64; wb++) {
        const ull fl = flg[wb];
        if (fl == 0ull) {
            if (tid < 64) {
                const ull supw = sup[wb];
                keepf[sord[wb * 64 + tid]] =
                    (((supw >> tid) & 1ull) == 0ull) ? 1.0f : 0.0f;
            }
            continue;
        }

        {
            const char* src = (const char*)(rows + (size_t)wb * 64 * NW);
            cp_async16(smb + (uint32_t)tid * 16,          src + tid * 16);
            cp_async16(smb + (uint32_t)(tid + 1024) * 16, src + (tid + 1024) * 16);
            asm volatile("cp.async.commit_group;");
            asm volatile("cp.async.wait_group 0;");
        }
        __syncthreads();

        if (tid < 32) {
            ull supw = sup[wb];
            ull keepm;
            if (((fl >> wb) & 1ull) == 0ull) {
                keepm = ~supw;
            } else {
                keepm = 0ull;                       // redundant per-lane chain
                #pragma unroll 8
                for (int i = 0; i < 64; i++) {
                    const ull d = buf[i * 64 + wb];
                    const bool k = ((supw >> i) & 1ull) == 0ull;
                    if (k) { supw |= d; keepm |= 1ull << i; }
                }
            }
            const int t0 = wb * 64 + tid;
            keepf[sord[t0]]      = ((keepm >> tid)        & 1ull) ? 1.0f : 0.0f;
            keepf[sord[t0 + 32]] = ((keepm >> (tid + 32)) & 1ull) ? 1.0f : 0.0f;
            if (tid == 0) sh_keepm[0] = keepm;
        }
        __syncthreads();

        const ull keepm = sh_keepm[0];
        const int w   = tid & 63;
        const int sub = tid >> 6;
        if (w > wb && ((fl >> w) & 1ull)) {
            ull p = 0ull;
            #pragma unroll
            for (int r = 0; r < 4; r++) {
                const int i = sub * 4 + r;
                if ((keepm >> i) & 1ull) p |= buf[i * 64 + w];
            }
            if (p) atomicOr(&sup[w], p);
        }
        __syncthreads();
    }
}

// ---------------- 5. masked tokens + keep tail (no dependent chain) ---------
__global__ void mask_kernel(const float4* __restrict__ tok, float* __restrict__ out,
                            int tail_count) {
    const int idx = blockIdx.x * blockDim.x + threadIdx.x;
    const int total4 = B * N * (D / 4);
    if (idx < total4) {
        const float k = g_keepf[idx >> 6];          // independent, L2-resident
        float4 v = tok[idx];                        // independent
        v.x *= k; v.y *= k; v.z *= k; v.w *= k;
        ((float4*)out)[idx] = v;
    } else {
        const int t = idx - total4;                 // tail: keep floats, original order
        if (t < tail_count) out[(size_t)B * N * D + t] = g_keepf[t];
    }
}

// ---------------- launch -----------------------------------------------------
extern "C" void kernel_launch(void* const* d_in, const int* in_sizes, int n_in,
                              void* d_out, int out_size) {
    const float* tokens = (const float*)d_in[0];
    const float* scores = (const float*)d_in[1];
    float* out = (float*)d_out;

    cudaFuncSetAttribute(sim_bits_kernel,
                         cudaFuncAttributeMaxDynamicSharedMemorySize, SIM_SMEM);
    cudaFuncSetAttribute(scan_kernel,
                         cudaFuncAttributeMaxDynamicSharedMemorySize, SCAN_SMEM);

    { dim3 grid(B, 32); rank_kernel<<<grid, 512>>>(scores); }

    {
        const int warps  = B * N;
        const int blocks = (warps * 32 + 255) / 256;
        norm_gather_kernel<<<blocks, 256>>>(tokens);
    }

    { dim3 grid(NPAIR, B); sim_bits_kernel<<<grid, 256, SIM_SMEM>>>(); }

    scan_kernel<<<B, 1024, SCAN_SMEM>>>();

    {
        const long long bnd = (long long)B * N * D;
        int tail = 0;
        if ((long long)out_size > bnd) {
            tail = (int)((long long)out_size - bnd);
            if (tail > B * N) tail = B * N;
        }
        const int total = B * N * (D / 4) + tail;
        mask_kernel<<<(total + 255) / 256, 256>>>((const float4*)tokens, out, tail);
    }
}